// round 13
// baseline (speedup 1.0000x reference)
#include <cuda_runtime.h>
#include <cuda_bf16.h>
#include <cstdint>

// LinearAttentionTriton (all-HMMA):
//   M_t (bf16 hi/lo) + fp32 S-partials  -- kA (persistent, mma.sync bf16 hi/lo)
//   S (bf16 hi/lo, transposed)          -- kB2 (deterministic reduce of fp32 partials)
//   out_t = (Q_t @ M_t) @ S             -- kQO (mma.sync bf16 hi/lo)
// N = 262144, D = 64, TRUNK = 128, T = 2048.

#define D 64
#define TRUNK 128
#define T_TRUNKS 2048
#define GRID_A 444            // 148 SMs * 3 CTAs

__device__ __align__(16) uint32_t g_mh32[T_TRUNKS * 2048];   // M^T hi, bf16x2 packed (16 MB)
__device__ __align__(16) uint32_t g_ml32[T_TRUNKS * 2048];   // M^T lo (16 MB)
__device__ __align__(16) float g_red[512 * D * D];           // fp32 S partials per kA CTA
__device__ __align__(16) __nv_bfloat16 g_sh[D * D];          // S^T hi
__device__ __align__(16) __nv_bfloat16 g_sl[D * D];          // S^T lo

// ---------------- common helpers ----------------
__device__ __forceinline__ uint32_t smem_u32(const void* p) {
    uint32_t a;
    asm("{ .reg .u64 t; cvta.to.shared.u64 t, %1; cvt.u32.u64 %0, t; }"
        : "=r"(a) : "l"(p));
    return a;
}
#define LDSM_X4(r0, r1, r2, r3, a) \
    asm volatile("ldmatrix.sync.aligned.m8n8.x4.shared.b16 {%0,%1,%2,%3}, [%4];" \
                 : "=r"(r0), "=r"(r1), "=r"(r2), "=r"(r3) : "r"(a))
#define LDSM_X2(r0, r1, a) \
    asm volatile("ldmatrix.sync.aligned.m8n8.x2.shared.b16 {%0,%1}, [%2];" \
                 : "=r"(r0), "=r"(r1) : "r"(a))
#define LDSM_X4_T(r0, r1, r2, r3, a) \
    asm volatile("ldmatrix.sync.aligned.m8n8.x4.trans.shared.b16 {%0,%1,%2,%3}, [%4];" \
                 : "=r"(r0), "=r"(r1), "=r"(r2), "=r"(r3) : "r"(a))
#define LDSM_X2_T(r0, r1, a) \
    asm volatile("ldmatrix.sync.aligned.m8n8.x2.trans.shared.b16 {%0,%1}, [%2];" \
                 : "=r"(r0), "=r"(r1) : "r"(a))
#define MMA16816(d, a, b) \
    asm volatile("mma.sync.aligned.m16n8k16.row.col.f32.bf16.bf16.f32 " \
                 "{%0,%1,%2,%3}, {%4,%5,%6,%7}, {%8,%9}, {%0,%1,%2,%3};" \
                 : "+f"((d)[0]), "+f"((d)[1]), "+f"((d)[2]), "+f"((d)[3]) \
                 : "r"((a)[0]), "r"((a)[1]), "r"((a)[2]), "r"((a)[3]), \
                   "r"((b)[0]), "r"((b)[1]))

// pack (x,y) -> bf16x2 hi word + bf16x2 lo-residual word (x in lower half)
__device__ __forceinline__ void pack_hl(float x, float y, uint32_t& h2, uint32_t& l2) {
    asm("cvt.rn.bf16x2.f32 %0, %1, %2;" : "=r"(h2) : "f"(y), "f"(x));
    const float fx = __uint_as_float(h2 << 16);
    const float fy = __uint_as_float(h2 & 0xffff0000u);
    asm("cvt.rn.bf16x2.f32 %0, %1, %2;" : "=r"(l2) : "f"(y - fy), "f"(x - fx));
}
// float4 -> 8B hi store + 8B lo store
__device__ __forceinline__ void split_quad(char* ph, char* pl, float4 v) {
    uint2 h, l;
    pack_hl(v.x, v.y, h.x, l.x);
    pack_hl(v.z, v.w, h.y, l.y);
    *(uint2*)ph = h;
    *(uint2*)pl = l;
}
__device__ __forceinline__ void split_pair(char* ph, char* pl, float x, float y) {
    uint32_t h2, l2;
    pack_hl(x, y, h2, l2);
    *(uint32_t*)ph = h2;
    *(uint32_t*)pl = l2;
}

// ---------------- kA: persistent, M^T via mma.sync (8 warps: 4m x 2n) ----------------
// out[m=e][n=d] = sum_r V[r][e] K[r][d]  (A = V^T, B = K^T; natural [r][.] storage)
// smem: Kh, Kl, Vh, Vl each [128][72] bf16 = 72 KB -> 3 CTAs/SM.
#define KA_STRB 144
#define KA_KH 0
#define KA_KL 18432
#define KA_VH 36864
#define KA_VL 55296
#define KA_SMEM 73728

__global__ void __launch_bounds__(256) kA(const float* __restrict__ Kg,
                                          const float* __restrict__ Vg) {
    extern __shared__ __align__(16) char sm[];
    const uint32_t sb = smem_u32(sm);
    const int tid = threadIdx.x, lane = tid & 31, wid = tid >> 5;

    const int mt = wid & 3;            // m-tile: rows e = mt*16..+16
    const int nh = wid >> 2;           // n-half: cols d = nh*32..+32
    const int m0 = mt * 16;

    const uint32_t aBase = sb + KA_VH
        + (uint32_t)(((lane & 7) + ((lane >> 4) << 3)) * KA_STRB)
        + (uint32_t)((m0 + ((lane >> 3) & 1) * 8) * 2);
    const uint32_t bBase = sb + KA_KH
        + (uint32_t)(((lane & 7) + ((lane >> 3) & 1) * 8) * KA_STRB)
        + (uint32_t)(nh * 4 * 16);

    float sum[4][4];
#pragma unroll
    for (int n = 0; n < 4; ++n)
#pragma unroll
        for (int j = 0; j < 4; ++j) sum[n][j] = 0.0f;

    const int g = lane >> 2, tc = lane & 3;
    bool first = true;

    for (int t = blockIdx.x; t < T_TRUNKS; t += GRID_A) {
        if (!first) __syncthreads();
        first = false;

        const float4* K4 = (const float4*)Kg + (long)t * 2048;
        const float4* V4 = (const float4*)Vg + (long)t * 2048;
#pragma unroll
        for (int i = tid; i < 2048; i += 256) {
            const int off = (i >> 4) * KA_STRB + ((i & 15) << 3);
            split_quad(sm + KA_KH + off, sm + KA_KL + off, K4[i]);
            split_quad(sm + KA_VH + off, sm + KA_VL + off, V4[i]);
        }
        __syncthreads();

        float acc[4][4];
#pragma unroll
        for (int n = 0; n < 4; ++n)
#pragma unroll
            for (int j = 0; j < 4; ++j) acc[n][j] = 0.0f;

#pragma unroll
        for (int k0 = 0; k0 < 128; k0 += 16) {
            uint32_t ah[4], al[4];
            const uint32_t aa = aBase + (uint32_t)(k0 * KA_STRB);
            LDSM_X4_T(ah[0], ah[1], ah[2], ah[3], aa);
            LDSM_X4_T(al[0], al[1], al[2], al[3], aa + (KA_VL - KA_VH));
#pragma unroll
            for (int n = 0; n < 4; ++n) {
                uint32_t bh[2], bl[2];
                const uint32_t ba = bBase + (uint32_t)(k0 * KA_STRB) + (uint32_t)(n * 16);
                LDSM_X2_T(bh[0], bh[1], ba);
                LDSM_X2_T(bl[0], bl[1], ba + (KA_KL - KA_KH));
                MMA16816(acc[n], ah, bh);
                MMA16816(acc[n], ah, bl);
                MMA16816(acc[n], al, bh);
            }
        }

        // write M^T bf16 hi/lo + accumulate fp32 S partial
        uint32_t* mh = g_mh32 + (long)t * 2048;
        uint32_t* ml = g_ml32 + (long)t * 2048;
#pragma unroll
        for (int n = 0; n < 4; ++n) {
            const int col = nh * 32 + n * 8 + tc * 2;
            uint32_t h2, l2;
            pack_hl(acc[n][0], acc[n][1], h2, l2);
            mh[(m0 + g) * 32 + (col >> 1)] = h2;
            ml[(m0 + g) * 32 + (col >> 1)] = l2;
            pack_hl(acc[n][2], acc[n][3], h2, l2);
            mh[(m0 + g + 8) * 32 + (col >> 1)] = h2;
            ml[(m0 + g + 8) * 32 + (col >> 1)] = l2;
#pragma unroll
            for (int j = 0; j < 4; ++j) sum[n][j] += acc[n][j];
        }
    }

    float* red = g_red + (long)blockIdx.x * 4096;
#pragma unroll
    for (int n = 0; n < 4; ++n) {
        const int col = nh * 32 + n * 8 + tc * 2;
        float2 v0; v0.x = sum[n][0]; v0.y = sum[n][1];
        float2 v1; v1.x = sum[n][2]; v1.y = sum[n][3];
        *(float2*)&red[(m0 + g) * 64 + col]     = v0;
        *(float2*)&red[(m0 + g + 8) * 64 + col] = v1;
    }
}

// ---------------- kB2: reduce partials; store S^T as bf16 hi/lo ----------------
// partial rows hold M^T => idx = c*64+e sums to S[c][e]; store at [e*64+c].
__global__ void __launch_bounds__(256) kB2() {
    const int idx = blockIdx.x * 256 + threadIdx.x;   // idx = c*64 + e
    float s = 0.0f;
    for (int b = 0; b < GRID_A; ++b) s += g_red[(long)b * 4096 + idx];
    const int c = idx >> 6, e = idx & 63;
    const __nv_bfloat16 h = __float2bfloat16_rn(s);
    g_sh[e * 64 + c] = h;
    g_sl[e * 64 + c] = __float2bfloat16_rn(s - __bfloat162float(h));
}

// ---------------- kQO: mma.sync bf16 hi/lo split ----------------
#define AH_OFF 0
#define AL_OFF 18432
#define BH_OFF 36864
#define BL_OFF 46080
#define QO_SMEM 55296
#define ASTR 72

__device__ __forceinline__ void gemm_bf16(uint32_t sb, float acc[2][8][4],
                                          int lane, int wid) {
    const uint32_t aRowByte = (uint32_t)((wid * 32 + (lane & 15)) * (ASTR * 2));
    const uint32_t aColByte = (uint32_t)((lane >> 4) * 16);
    const uint32_t bRowByte = (uint32_t)((lane & 7) * (ASTR * 2));
    const uint32_t bColByte = (uint32_t)(((lane >> 3) & 1) * 16);

#pragma unroll
    for (int k0 = 0; k0 < 64; k0 += 16) {
        const uint32_t kByte = (uint32_t)(k0 * 2);
        uint32_t bh[8][2], bl[8][2];
#pragma unroll
        for (int n = 0; n < 8; ++n) {
            const uint32_t ba = sb + BH_OFF + (uint32_t)(n * 8 * ASTR * 2)
                                + bRowByte + kByte + bColByte;
            LDSM_X2(bh[n][0], bh[n][1], ba);
            LDSM_X2(bl[n][0], bl[n][1], ba + (BL_OFF - BH_OFF));
        }
#pragma unroll
        for (int s = 0; s < 2; ++s) {
            const uint32_t aa = sb + AH_OFF + aRowByte + (uint32_t)(s * 16 * ASTR * 2)
                                + kByte + aColByte;
            uint32_t ah[4], al[4];
            LDSM_X4(ah[0], ah[1], ah[2], ah[3], aa);
            LDSM_X4(al[0], al[1], al[2], al[3], aa + (AL_OFF - AH_OFF));
#pragma unroll
            for (int n = 0; n < 8; ++n) {
                MMA16816(acc[s][n], ah, bh[n]);
                MMA16816(acc[s][n], ah, bl[n]);
                MMA16816(acc[s][n], al, bh[n]);
            }
        }
    }
}

__global__ void __launch_bounds__(128, 4) kQO(const float* __restrict__ Qg,
                                              float* __restrict__ outg) {
    extern __shared__ __align__(16) char sm[];
    const uint32_t sb = smem_u32(sm);
    const int tid = threadIdx.x, lane = tid & 31, wid = tid >> 5;
    const long t = blockIdx.x;

    // Q -> Ah/Al (split, wide stores)
    const float4* Q4 = (const float4*)Qg + t * 2048;
#pragma unroll
    for (int i = tid; i < 2048; i += 128) {
        const int off = (i >> 4) * (ASTR * 2) + ((i & 15) << 3);
        split_quad(sm + AH_OFF + off, sm + AL_OFF + off, Q4[i]);
    }
    // Mh/Ml -> Bh/Bl: raw uint4 copies into padded rows (no conversion!)
    const uint4* MH4 = (const uint4*)g_mh32 + t * 512;
    const uint4* ML4 = (const uint4*)g_ml32 + t * 512;
#pragma unroll
    for (int i = tid; i < 512; i += 128) {
        const int off = (i >> 3) * (ASTR * 2) + ((i & 7) << 4);
        *(uint4*)(sm + BH_OFF + off) = MH4[i];
        *(uint4*)(sm + BL_OFF + off) = ML4[i];
    }
    __syncthreads();

    float acc[2][8][4];
#pragma unroll
    for (int s = 0; s < 2; ++s)
#pragma unroll
        for (int n = 0; n < 8; ++n)
#pragma unroll
            for (int j = 0; j < 4; ++j) acc[s][n][j] = 0.0f;

    gemm_bf16(sb, acc, lane, wid);   // GEMM1: P = Q @ M
    __syncthreads();

    // P fragments -> Ah/Al; Sh/Sl -> Bh/Bl (raw copies)
    const int g = lane >> 2, tc = lane & 3;
#pragma unroll
    for (int s = 0; s < 2; ++s)
#pragma unroll
        for (int n = 0; n < 8; ++n) {
            const int col = n * 8 + tc * 2;
            const int row1 = wid * 32 + s * 16 + g;
            const int off1 = row1 * (ASTR * 2) + col * 2;
            const int off2 = off1 + 8 * (ASTR * 2);
            split_pair(sm + AH_OFF + off1, sm + AL_OFF + off1,
                       acc[s][n][0], acc[s][n][1]);
            split_pair(sm + AH_OFF + off2, sm + AL_OFF + off2,
                       acc[s][n][2], acc[s][n][3]);
        }
    {
        const uint4* SH4 = (const uint4*)g_sh;
        const uint4* SL4 = (const uint4*)g_sl;
#pragma unroll
        for (int i = tid; i < 512; i += 128) {
            const int off = (i >> 3) * (ASTR * 2) + ((i & 7) << 4);
            *(uint4*)(sm + BH_OFF + off) = SH4[i];
            *(uint4*)(sm + BL_OFF + off) = SL4[i];
        }
    }
    __syncthreads();

#pragma unroll
    for (int s = 0; s < 2; ++s)
#pragma unroll
        for (int n = 0; n < 8; ++n)
#pragma unroll
            for (int j = 0; j < 4; ++j) acc[s][n][j] = 0.0f;

    gemm_bf16(sb, acc, lane, wid);   // GEMM2: out = P @ S

    float* outp = outg + t * (TRUNK * D);
#pragma unroll
    for (int s = 0; s < 2; ++s)
#pragma unroll
        for (int n = 0; n < 8; ++n) {
            const int col = n * 8 + tc * 2;
            const int row1 = wid * 32 + s * 16 + g;
            float2 v0; v0.x = acc[s][n][0]; v0.y = acc[s][n][1];
            float2 v1; v1.x = acc[s][n][2]; v1.y = acc[s][n][3];
            *(float2*)&outp[row1 * 64 + col]       = v0;
            *(float2*)&outp[(row1 + 8) * 64 + col] = v1;
        }
}

extern "C" void kernel_launch(void* const* d_in, const int* in_sizes, int n_in,
                              void* d_out, int out_size) {
    const float* Q = (const float*)d_in[0];
    const float* K = (const float*)d_in[1];
    const float* V = (const float*)d_in[2];
    float* out = (float*)d_out;

    cudaFuncSetAttribute(kA,  cudaFuncAttributeMaxDynamicSharedMemorySize, KA_SMEM);
    cudaFuncSetAttribute(kQO, cudaFuncAttributeMaxDynamicSharedMemorySize, QO_SMEM);

    kA<<<GRID_A, 256, KA_SMEM>>>(K, V);
    kB2<<<16, 256>>>();
    kQO<<<T_TRUNKS, 128, QO_SMEM>>>(Q, out);
}

// round 14
// speedup vs baseline: 1.0187x; 1.0187x over previous
#include <cuda_runtime.h>
#include <cuda_bf16.h>
#include <cstdint>

// LinearAttentionTriton (all-HMMA):
//   M_t (bf16 hi/lo) + fp32 S-partials  -- kA (persistent, mma.sync bf16 hi/lo)
//   S (bf16 hi/lo, transposed)          -- kB2 (deterministic reduce)
//   out_t = (Q_t @ M_t) @ S             -- kQO (mma.sync; P kept in registers)
// N = 262144, D = 64, TRUNK = 128, T = 2048.

#define D 64
#define TRUNK 128
#define T_TRUNKS 2048
#define GRID_A 444            // 148 SMs * 3 CTAs

__device__ __align__(16) uint32_t g_mh32[T_TRUNKS * 2048];   // M^T hi (bf16x2)
__device__ __align__(16) uint32_t g_ml32[T_TRUNKS * 2048];   // M^T lo
__device__ __align__(16) float g_red[512 * D * D];           // fp32 S partials
__device__ __align__(16) __nv_bfloat16 g_sh[D * D];          // S^T hi
__device__ __align__(16) __nv_bfloat16 g_sl[D * D];          // S^T lo

// ---------------- common helpers ----------------
__device__ __forceinline__ uint32_t smem_u32(const void* p) {
    uint32_t a;
    asm("{ .reg .u64 t; cvta.to.shared.u64 t, %1; cvt.u32.u64 %0, t; }"
        : "=r"(a) : "l"(p));
    return a;
}
#define LDSM_X4(r0, r1, r2, r3, a) \
    asm volatile("ldmatrix.sync.aligned.m8n8.x4.shared.b16 {%0,%1,%2,%3}, [%4];" \
                 : "=r"(r0), "=r"(r1), "=r"(r2), "=r"(r3) : "r"(a))
#define LDSM_X2(r0, r1, a) \
    asm volatile("ldmatrix.sync.aligned.m8n8.x2.shared.b16 {%0,%1}, [%2];" \
                 : "=r"(r0), "=r"(r1) : "r"(a))
#define LDSM_X4_T(r0, r1, r2, r3, a) \
    asm volatile("ldmatrix.sync.aligned.m8n8.x4.trans.shared.b16 {%0,%1,%2,%3}, [%4];" \
                 : "=r"(r0), "=r"(r1), "=r"(r2), "=r"(r3) : "r"(a))
#define LDSM_X2_T(r0, r1, a) \
    asm volatile("ldmatrix.sync.aligned.m8n8.x2.trans.shared.b16 {%0,%1}, [%2];" \
                 : "=r"(r0), "=r"(r1) : "r"(a))
#define MMA16816(d, a, b) \
    asm volatile("mma.sync.aligned.m16n8k16.row.col.f32.bf16.bf16.f32 " \
                 "{%0,%1,%2,%3}, {%4,%5,%6,%7}, {%8,%9}, {%0,%1,%2,%3};" \
                 : "+f"((d)[0]), "+f"((d)[1]), "+f"((d)[2]), "+f"((d)[3]) \
                 : "r"((a)[0]), "r"((a)[1]), "r"((a)[2]), "r"((a)[3]), \
                   "r"((b)[0]), "r"((b)[1]))

__device__ __forceinline__ void pack_hl(float x, float y, uint32_t& h2, uint32_t& l2) {
    asm("cvt.rn.bf16x2.f32 %0, %1, %2;" : "=r"(h2) : "f"(y), "f"(x));
    const float fx = __uint_as_float(h2 << 16);
    const float fy = __uint_as_float(h2 & 0xffff0000u);
    asm("cvt.rn.bf16x2.f32 %0, %1, %2;" : "=r"(l2) : "f"(y - fy), "f"(x - fx));
}
__device__ __forceinline__ void split_quad(char* ph, char* pl, float4 v) {
    uint2 h, l;
    pack_hl(v.x, v.y, h.x, l.x);
    pack_hl(v.z, v.w, h.y, l.y);
    *(uint2*)ph = h;
    *(uint2*)pl = l;
}

// ---------------- kA: persistent, M^T via mma.sync (round-13, unchanged) ----------------
#define KA_STRB 144
#define KA_KH 0
#define KA_KL 18432
#define KA_VH 36864
#define KA_VL 55296
#define KA_SMEM 73728

__global__ void __launch_bounds__(256) kA(const float* __restrict__ Kg,
                                          const float* __restrict__ Vg) {
    extern __shared__ __align__(16) char sm[];
    const uint32_t sb = smem_u32(sm);
    const int tid = threadIdx.x, lane = tid & 31, wid = tid >> 5;

    const int mt = wid & 3;
    const int nh = wid >> 2;
    const int m0 = mt * 16;

    const uint32_t aBase = sb + KA_VH
        + (uint32_t)(((lane & 7) + ((lane >> 4) << 3)) * KA_STRB)
        + (uint32_t)((m0 + ((lane >> 3) & 1) * 8) * 2);
    const uint32_t bBase = sb + KA_KH
        + (uint32_t)(((lane & 7) + ((lane >> 3) & 1) * 8) * KA_STRB)
        + (uint32_t)(nh * 4 * 16);

    float sum[4][4];
#pragma unroll
    for (int n = 0; n < 4; ++n)
#pragma unroll
        for (int j = 0; j < 4; ++j) sum[n][j] = 0.0f;

    const int g = lane >> 2, tc = lane & 3;
    bool first = true;

    for (int t = blockIdx.x; t < T_TRUNKS; t += GRID_A) {
        if (!first) __syncthreads();
        first = false;

        const float4* K4 = (const float4*)Kg + (long)t * 2048;
        const float4* V4 = (const float4*)Vg + (long)t * 2048;
#pragma unroll
        for (int i = tid; i < 2048; i += 256) {
            const int off = (i >> 4) * KA_STRB + ((i & 15) << 3);
            split_quad(sm + KA_KH + off, sm + KA_KL + off, K4[i]);
            split_quad(sm + KA_VH + off, sm + KA_VL + off, V4[i]);
        }
        __syncthreads();

        float acc[4][4];
#pragma unroll
        for (int n = 0; n < 4; ++n)
#pragma unroll
            for (int j = 0; j < 4; ++j) acc[n][j] = 0.0f;

#pragma unroll
        for (int k0 = 0; k0 < 128; k0 += 16) {
            uint32_t ah[4], al[4];
            const uint32_t aa = aBase + (uint32_t)(k0 * KA_STRB);
            LDSM_X4_T(ah[0], ah[1], ah[2], ah[3], aa);
            LDSM_X4_T(al[0], al[1], al[2], al[3], aa + (KA_VL - KA_VH));
#pragma unroll
            for (int n = 0; n < 4; ++n) {
                uint32_t bh[2], bl[2];
                const uint32_t ba = bBase + (uint32_t)(k0 * KA_STRB) + (uint32_t)(n * 16);
                LDSM_X2_T(bh[0], bh[1], ba);
                LDSM_X2_T(bl[0], bl[1], ba + (KA_KL - KA_KH));
                MMA16816(acc[n], ah, bh);
                MMA16816(acc[n], ah, bl);
                MMA16816(acc[n], al, bh);
            }
        }

        uint32_t* mh = g_mh32 + (long)t * 2048;
        uint32_t* ml = g_ml32 + (long)t * 2048;
#pragma unroll
        for (int n = 0; n < 4; ++n) {
            const int col = nh * 32 + n * 8 + tc * 2;
            uint32_t h2, l2;
            pack_hl(acc[n][0], acc[n][1], h2, l2);
            mh[(m0 + g) * 32 + (col >> 1)] = h2;
            ml[(m0 + g) * 32 + (col >> 1)] = l2;
            pack_hl(acc[n][2], acc[n][3], h2, l2);
            mh[(m0 + g + 8) * 32 + (col >> 1)] = h2;
            ml[(m0 + g + 8) * 32 + (col >> 1)] = l2;
#pragma unroll
            for (int j = 0; j < 4; ++j) sum[n][j] += acc[n][j];
        }
    }

    float* red = g_red + (long)blockIdx.x * 4096;
#pragma unroll
    for (int n = 0; n < 4; ++n) {
        const int col = nh * 32 + n * 8 + tc * 2;
        float2 v0; v0.x = sum[n][0]; v0.y = sum[n][1];
        float2 v1; v1.x = sum[n][2]; v1.y = sum[n][3];
        *(float2*)&red[(m0 + g) * 64 + col]     = v0;
        *(float2*)&red[(m0 + g + 8) * 64 + col] = v1;
    }
}

// ---------------- kB2 (round-13, unchanged) ----------------
__global__ void __launch_bounds__(256) kB2() {
    const int idx = blockIdx.x * 256 + threadIdx.x;   // idx = c*64 + e
    float s = 0.0f;
    for (int b = 0; b < GRID_A; ++b) s += g_red[(long)b * 4096 + idx];
    const int c = idx >> 6, e = idx & 63;
    const __nv_bfloat16 h = __float2bfloat16_rn(s);
    g_sh[e * 64 + c] = h;
    g_sl[e * 64 + c] = __float2bfloat16_rn(s - __bfloat162float(h));
}

// ---------------- kQO: GEMM1 -> in-register P frags -> GEMM2 ----------------
#define AH_OFF 0
#define AL_OFF 18432
#define BH_OFF 36864
#define BL_OFF 46080
#define QO_SMEM 55296
#define ASTR 72

__global__ void __launch_bounds__(128, 4) kQO(const float* __restrict__ Qg,
                                              float* __restrict__ outg) {
    extern __shared__ __align__(16) char sm[];
    const uint32_t sb = smem_u32(sm);
    const int tid = threadIdx.x, lane = tid & 31, wid = tid >> 5;
    const long t = blockIdx.x;

    // Q -> Ah/Al; M -> BH/BL (raw copies)
    const float4* Q4 = (const float4*)Qg + t * 2048;
#pragma unroll
    for (int i = tid; i < 2048; i += 128) {
        const int off = (i >> 4) * (ASTR * 2) + ((i & 15) << 3);
        split_quad(sm + AH_OFF + off, sm + AL_OFF + off, Q4[i]);
    }
    const uint4* MH4 = (const uint4*)g_mh32 + t * 512;
    const uint4* ML4 = (const uint4*)g_ml32 + t * 512;
#pragma unroll
    for (int i = tid; i < 512; i += 128) {
        const int off = (i >> 3) * (ASTR * 2) + ((i & 7) << 4);
        *(uint4*)(sm + BH_OFF + off) = MH4[i];
        *(uint4*)(sm + BL_OFF + off) = ML4[i];
    }
    __syncthreads();

    // ---- GEMM1: P = Q @ M (hoisted B frags, as before) ----
    float acc[2][8][4];
#pragma unroll
    for (int s = 0; s < 2; ++s)
#pragma unroll
        for (int n = 0; n < 8; ++n)
#pragma unroll
            for (int j = 0; j < 4; ++j) acc[s][n][j] = 0.0f;

    const uint32_t aRowByte = (uint32_t)((wid * 32 + (lane & 15)) * (ASTR * 2));
    const uint32_t aColByte = (uint32_t)((lane >> 4) * 16);
    const uint32_t bRowByte = (uint32_t)((lane & 7) * (ASTR * 2));
    const uint32_t bColByte = (uint32_t)(((lane >> 3) & 1) * 16);

#pragma unroll
    for (int k0 = 0; k0 < 64; k0 += 16) {
        const uint32_t kByte = (uint32_t)(k0 * 2);
        uint32_t bh[8][2], bl[8][2];
#pragma unroll
        for (int n = 0; n < 8; ++n) {
            const uint32_t ba = sb + BH_OFF + (uint32_t)(n * 8 * ASTR * 2)
                                + bRowByte + kByte + bColByte;
            LDSM_X2(bh[n][0], bh[n][1], ba);
            LDSM_X2(bl[n][0], bl[n][1], ba + (BL_OFF - BH_OFF));
        }
#pragma unroll
        for (int s = 0; s < 2; ++s) {
            const uint32_t aa = sb + AH_OFF + aRowByte + (uint32_t)(s * 16 * ASTR * 2)
                                + kByte + aColByte;
            uint32_t ah[4], al[4];
            LDSM_X4(ah[0], ah[1], ah[2], ah[3], aa);
            LDSM_X4(al[0], al[1], al[2], al[3], aa + (AL_OFF - AH_OFF));
#pragma unroll
            for (int n = 0; n < 8; ++n) {
                MMA16816(acc[s][n], ah, bh[n]);
                MMA16816(acc[s][n], ah, bl[n]);
                MMA16816(acc[s][n], al, bh[n]);
            }
        }
    }

    // ---- convert P accumulators to A-fragments in registers ----
    // C-frag of tiles (2j, 2j+1) == A-frag of k-chunk j:
    //   a0 = pack(c0,c1)[2j], a1 = pack(c2,c3)[2j], a2 = pack(c0,c1)[2j+1], a3 = pack(c2,c3)[2j+1]
    uint32_t ph[2][8][2], pl[2][8][2];
#pragma unroll
    for (int s = 0; s < 2; ++s)
#pragma unroll
        for (int n = 0; n < 8; ++n) {
            pack_hl(acc[s][n][0], acc[s][n][1], ph[s][n][0], pl[s][n][0]);
            pack_hl(acc[s][n][2], acc[s][n][3], ph[s][n][1], pl[s][n][1]);
        }

    __syncthreads();   // all BH/BL (M) reads done
    // S -> BH/BL (raw copies)
    {
        const uint4* SH4 = (const uint4*)g_sh;
        const uint4* SL4 = (const uint4*)g_sl;
#pragma unroll
        for (int i = tid; i < 512; i += 128) {
            const int off = (i >> 3) * (ASTR * 2) + ((i & 7) << 4);
            *(uint4*)(sm + BH_OFF + off) = SH4[i];
            *(uint4*)(sm + BL_OFF + off) = SL4[i];
        }
    }
    __syncthreads();

    // ---- GEMM2: out = P @ S (A from registers, B per-n loads) ----
    const int g = lane >> 2, tc = lane & 3;
    float* outp = outg + t * (TRUNK * D);
#pragma unroll
    for (int s = 0; s < 2; ++s) {
        float accO[8][4];
#pragma unroll
        for (int n = 0; n < 8; ++n)
#pragma unroll
            for (int j = 0; j < 4; ++j) accO[n][j] = 0.0f;

#pragma unroll
        for (int j = 0; j < 4; ++j) {
            uint32_t ah[4] = {ph[s][2 * j][0], ph[s][2 * j][1],
                              ph[s][2 * j + 1][0], ph[s][2 * j + 1][1]};
            uint32_t al[4] = {pl[s][2 * j][0], pl[s][2 * j][1],
                              pl[s][2 * j + 1][0], pl[s][2 * j + 1][1]};
            const uint32_t kByte = (uint32_t)(j * 32);   // 16 k * 2 B
#pragma unroll
            for (int n = 0; n < 8; ++n) {
                uint32_t bh[2], bl[2];
                const uint32_t ba = sb + BH_OFF + (uint32_t)(n * 8 * ASTR * 2)
                                    + bRowByte + kByte + bColByte;
                LDSM_X2(bh[0], bh[1], ba);
                LDSM_X2(bl[0], bl[1], ba + (BL_OFF - BH_OFF));
                MMA16816(accO[n], ah, bh);
                MMA16816(accO[n], ah, bl);
                MMA16816(accO[n], al, bh);
            }
        }

#pragma unroll
        for (int n = 0; n < 8; ++n) {
            const int col = n * 8 + tc * 2;
            const int row1 = wid * 32 + s * 16 + g;
            float2 v0; v0.x = accO[n][0]; v0.y = accO[n][1];
            float2 v1; v1.x = accO[n][2]; v1.y = accO[n][3];
            *(float2*)&outp[row1 * 64 + col]       = v0;
            *(float2*)&outp[(row1 + 8) * 64 + col] = v1;
        }
    }
}

extern "C" void kernel_launch(void* const* d_in, const int* in_sizes, int n_in,
                              void* d_out, int out_size) {
    const float* Q = (const float*)d_in[0];
    const float* K = (const float*)d_in[1];
    const float* V = (const float*)d_in[2];
    float* out = (float*)d_out;

    cudaFuncSetAttribute(kA,  cudaFuncAttributeMaxDynamicSharedMemorySize, KA_SMEM);
    cudaFuncSetAttribute(kQO, cudaFuncAttributeMaxDynamicSharedMemorySize, QO_SMEM);

    kA<<<GRID_A, 256, KA_SMEM>>>(K, V);
    kB2<<<16, 256>>>();
    kQO<<<T_TRUNKS, 128, QO_SMEM>>>(Q, out);
}

// round 16
// speedup vs baseline: 1.0247x; 1.0059x over previous
#include <cuda_runtime.h>
#include <cuda_bf16.h>
#include <cstdint>

// LinearAttentionTriton (all-HMMA):
//   M_t (bf16 hi/lo) + fp32 S-partials  -- kA (persistent, double-buffered stages)
//   S (bf16 hi/lo, transposed)          -- kB2 (deterministic reduce)
//   out_t = (Q_t @ M_t) @ S             -- kQO (mma.sync; P kept in registers)
// N = 262144, D = 64, TRUNK = 128, T = 2048.

#define D 64
#define TRUNK 128
#define T_TRUNKS 2048
#define GRID_A 444            // 148 SMs * 3 CTAs

__device__ __align__(16) uint32_t g_mh32[T_TRUNKS * 2048];   // M^T hi (bf16x2)
__device__ __align__(16) uint32_t g_ml32[T_TRUNKS * 2048];   // M^T lo
__device__ __align__(16) float g_red[512 * D * D];           // fp32 S partials
__device__ __align__(16) __nv_bfloat16 g_sh[D * D];          // S^T hi
__device__ __align__(16) __nv_bfloat16 g_sl[D * D];          // S^T lo

// ---------------- common helpers ----------------
__device__ __forceinline__ uint32_t smem_u32(const void* p) {
    uint32_t a;
    asm("{ .reg .u64 t; cvta.to.shared.u64 t, %1; cvt.u32.u64 %0, t; }"
        : "=r"(a) : "l"(p));
    return a;
}
#define LDSM_X4(r0, r1, r2, r3, a) \
    asm volatile("ldmatrix.sync.aligned.m8n8.x4.shared.b16 {%0,%1,%2,%3}, [%4];" \
                 : "=r"(r0), "=r"(r1), "=r"(r2), "=r"(r3) : "r"(a))
#define LDSM_X2(r0, r1, a) \
    asm volatile("ldmatrix.sync.aligned.m8n8.x2.shared.b16 {%0,%1}, [%2];" \
                 : "=r"(r0), "=r"(r1) : "r"(a))
#define LDSM_X4_T(r0, r1, r2, r3, a) \
    asm volatile("ldmatrix.sync.aligned.m8n8.x4.trans.shared.b16 {%0,%1,%2,%3}, [%4];" \
                 : "=r"(r0), "=r"(r1), "=r"(r2), "=r"(r3) : "r"(a))
#define LDSM_X2_T(r0, r1, a) \
    asm volatile("ldmatrix.sync.aligned.m8n8.x2.trans.shared.b16 {%0,%1}, [%2];" \
                 : "=r"(r0), "=r"(r1) : "r"(a))
#define MMA16816(d, a, b) \
    asm volatile("mma.sync.aligned.m16n8k16.row.col.f32.bf16.bf16.f32 " \
                 "{%0,%1,%2,%3}, {%4,%5,%6,%7}, {%8,%9}, {%0,%1,%2,%3};" \
                 : "+f"((d)[0]), "+f"((d)[1]), "+f"((d)[2]), "+f"((d)[3]) \
                 : "r"((a)[0]), "r"((a)[1]), "r"((a)[2]), "r"((a)[3]), \
                   "r"((b)[0]), "r"((b)[1]))

__device__ __forceinline__ void pack_hl(float x, float y, uint32_t& h2, uint32_t& l2) {
    asm("cvt.rn.bf16x2.f32 %0, %1, %2;" : "=r"(h2) : "f"(y), "f"(x));
    const float fx = __uint_as_float(h2 << 16);
    const float fy = __uint_as_float(h2 & 0xffff0000u);
    asm("cvt.rn.bf16x2.f32 %0, %1, %2;" : "=r"(l2) : "f"(y - fy), "f"(x - fx));
}
__device__ __forceinline__ void split_quad(char* ph, char* pl, float4 v) {
    uint2 h, l;
    pack_hl(v.x, v.y, h.x, l.x);
    pack_hl(v.z, v.w, h.y, l.y);
    *(uint2*)ph = h;
    *(uint2*)pl = l;
}

// ---------------- kA: persistent, double-buffered 64-row stages ----------------
// out[m=e][n=d] = sum_r V[r][e] K[r][d]  (A = V^T, B = K^T)
// smem: 2 stage buffers x (Kh,Kl,Vh,Vl of 64 rows x 144 B) = 2 x 36864 = 72 KB.
// A 64-row stage of one matrix = 1024 float4 -> 4 float4 per thread (256 thr).
#define KA_STRB 144
#define ST_KH 0
#define ST_KL 9216
#define ST_VH 18432
#define ST_VL 27648
#define KA_STAGE 36864
#define KA_SMEM 73728

__global__ void __launch_bounds__(256, 2) kA(const float* __restrict__ Kg,
                                             const float* __restrict__ Vg) {
    extern __shared__ __align__(16) char sm[];
    const uint32_t sb = smem_u32(sm);
    const int tid = threadIdx.x, lane = tid & 31, wid = tid >> 5;

    const int mt = wid & 3;            // m-tile: rows e = mt*16..+16
    const int nh = wid >> 2;           // n-half: cols d = nh*32..+32
    const int m0 = mt * 16;

    // within-stage ldmatrix offsets
    const uint32_t aOff = ST_VH
        + (uint32_t)(((lane & 7) + ((lane >> 4) << 3)) * KA_STRB)
        + (uint32_t)((m0 + ((lane >> 3) & 1) * 8) * 2);
    const uint32_t bOff = ST_KH
        + (uint32_t)(((lane & 7) + ((lane >> 3) & 1) * 8) * KA_STRB)
        + (uint32_t)(nh * 4 * 16);
    // within-stage store offsets: i = tid + k*256, k = 0..3
    int so[4];
#pragma unroll
    for (int k = 0; k < 4; ++k) {
        const int i = tid + k * 256;
        so[k] = (i >> 4) * KA_STRB + ((i & 15) << 3);
    }

    float sum[4][4];
#pragma unroll
    for (int n = 0; n < 4; ++n)
#pragma unroll
        for (int j = 0; j < 4; ++j) sum[n][j] = 0.0f;

    float acc[4][4];
    const int g = lane >> 2, tc = lane & 3;

    const int nTr = (T_TRUNKS - blockIdx.x + GRID_A - 1) / GRID_A;
    const int S = nTr * 2;             // 64-row stages

    float4 kr[4], vr[4];
    // prologue: load + store stage 0 into buffer 0
    {
        const float4* K4 = (const float4*)Kg + (long)blockIdx.x * 2048;
        const float4* V4 = (const float4*)Vg + (long)blockIdx.x * 2048;
#pragma unroll
        for (int k = 0; k < 4; ++k) { kr[k] = K4[tid + k * 256]; vr[k] = V4[tid + k * 256]; }
        char* base = sm;
#pragma unroll
        for (int k = 0; k < 4; ++k) {
            split_quad(base + ST_KH + so[k], base + ST_KL + so[k], kr[k]);
            split_quad(base + ST_VH + so[k], base + ST_VL + so[k], vr[k]);
        }
    }
    __syncthreads();

    for (int j = 0; j < S; ++j) {
        const int half = j & 1;
        const long t = (long)blockIdx.x + (long)(j >> 1) * GRID_A;

        // prefetch next stage into registers (hidden behind MMA below)
        const bool hasNext = (j + 1 < S);
        if (hasNext) {
            const int jn = j + 1;
            const long tn = (long)blockIdx.x + (long)(jn >> 1) * GRID_A;
            const long rbase = tn * 2048 + (long)(jn & 1) * 1024;
            const float4* K4 = (const float4*)Kg + rbase;
            const float4* V4 = (const float4*)Vg + rbase;
#pragma unroll
            for (int k = 0; k < 4; ++k) { kr[k] = K4[tid + k * 256]; vr[k] = V4[tid + k * 256]; }
        }

        if (half == 0) {
#pragma unroll
            for (int n = 0; n < 4; ++n)
#pragma unroll
                for (int jj = 0; jj < 4; ++jj) acc[n][jj] = 0.0f;
        }

        // MMA over this stage's 64 k-rows
        const uint32_t stBase = sb + (uint32_t)((j & 1) * KA_STAGE);
#pragma unroll
        for (int k0 = 0; k0 < 64; k0 += 16) {
            uint32_t ah[4], al[4];
            const uint32_t aa = stBase + aOff + (uint32_t)(k0 * KA_STRB);
            LDSM_X4_T(ah[0], ah[1], ah[2], ah[3], aa);
            LDSM_X4_T(al[0], al[1], al[2], al[3], aa + (ST_VL - ST_VH));
#pragma unroll
            for (int n = 0; n < 4; ++n) {
                uint32_t bh[2], bl[2];
                const uint32_t ba = stBase + bOff + (uint32_t)(k0 * KA_STRB)
                                    + (uint32_t)(n * 16);
                LDSM_X2_T(bh[0], bh[1], ba);
                LDSM_X2_T(bl[0], bl[1], ba + (ST_KL - ST_KH));
                MMA16816(acc[n], ah, bh);
                MMA16816(acc[n], ah, bl);
                MMA16816(acc[n], al, bh);
            }
        }

        // convert + store next stage (regs -> other buffer)
        if (hasNext) {
            char* base = sm + ((j + 1) & 1) * KA_STAGE;
#pragma unroll
            for (int k = 0; k < 4; ++k) {
                split_quad(base + ST_KH + so[k], base + ST_KL + so[k], kr[k]);
                split_quad(base + ST_VH + so[k], base + ST_VL + so[k], vr[k]);
            }
        }

        // trunk epilogue after second half
        if (half == 1) {
            uint32_t* mh = g_mh32 + t * 2048;
            uint32_t* ml = g_ml32 + t * 2048;
#pragma unroll
            for (int n = 0; n < 4; ++n) {
                const int col = nh * 32 + n * 8 + tc * 2;
                uint32_t h2, l2;
                pack_hl(acc[n][0], acc[n][1], h2, l2);
                mh[(m0 + g) * 32 + (col >> 1)] = h2;
                ml[(m0 + g) * 32 + (col >> 1)] = l2;
                pack_hl(acc[n][2], acc[n][3], h2, l2);
                mh[(m0 + g + 8) * 32 + (col >> 1)] = h2;
                ml[(m0 + g + 8) * 32 + (col >> 1)] = l2;
#pragma unroll
                for (int jj = 0; jj < 4; ++jj) sum[n][jj] += acc[n][jj];
            }
        }
        __syncthreads();
    }

    float* red = g_red + (long)blockIdx.x * 4096;
#pragma unroll
    for (int n = 0; n < 4; ++n) {
        const int col = nh * 32 + n * 8 + tc * 2;
        float2 v0; v0.x = sum[n][0]; v0.y = sum[n][1];
        float2 v1; v1.x = sum[n][2]; v1.y = sum[n][3];
        *(float2*)&red[(m0 + g) * 64 + col]     = v0;
        *(float2*)&red[(m0 + g + 8) * 64 + col] = v1;
    }
}

// ---------------- kB2 (unchanged) ----------------
__global__ void __launch_bounds__(256) kB2() {
    const int idx = blockIdx.x * 256 + threadIdx.x;   // idx = c*64 + e
    float s = 0.0f;
    for (int b = 0; b < GRID_A; ++b) s += g_red[(long)b * 4096 + idx];
    const int c = idx >> 6, e = idx & 63;
    const __nv_bfloat16 h = __float2bfloat16_rn(s);
    g_sh[e * 64 + c] = h;
    g_sl[e * 64 + c] = __float2bfloat16_rn(s - __bfloat162float(h));
}

// ---------------- kQO: round-14 (in-register P), unchanged ----------------
#define AH_OFF 0
#define AL_OFF 18432
#define BH_OFF 36864
#define BL_OFF 46080
#define QO_SMEM 55296
#define ASTR 72

__global__ void __launch_bounds__(128, 4) kQO(const float* __restrict__ Qg,
                                              float* __restrict__ outg) {
    extern __shared__ __align__(16) char sm[];
    const uint32_t sb = smem_u32(sm);
    const int tid = threadIdx.x, lane = tid & 31, wid = tid >> 5;
    const long t = blockIdx.x;

    const float4* Q4 = (const float4*)Qg + t * 2048;
#pragma unroll
    for (int i = tid; i < 2048; i += 128) {
        const int off = (i >> 4) * (ASTR * 2) + ((i & 15) << 3);
        split_quad(sm + AH_OFF + off, sm + AL_OFF + off, Q4[i]);
    }
    const uint4* MH4 = (const uint4*)g_mh32 + t * 512;
    const uint4* ML4 = (const uint4*)g_ml32 + t * 512;
#pragma unroll
    for (int i = tid; i < 512; i += 128) {
        const int off = (i >> 3) * (ASTR * 2) + ((i & 7) << 4);
        *(uint4*)(sm + BH_OFF + off) = MH4[i];
        *(uint4*)(sm + BL_OFF + off) = ML4[i];
    }
    __syncthreads();

    float acc[2][8][4];
#pragma unroll
    for (int s = 0; s < 2; ++s)
#pragma unroll
        for (int n = 0; n < 8; ++n)
#pragma unroll
            for (int j = 0; j < 4; ++j) acc[s][n][j] = 0.0f;

    const uint32_t aRowByte = (uint32_t)((wid * 32 + (lane & 15)) * (ASTR * 2));
    const uint32_t aColByte = (uint32_t)((lane >> 4) * 16);
    const uint32_t bRowByte = (uint32_t)((lane & 7) * (ASTR * 2));
    const uint32_t bColByte = (uint32_t)(((lane >> 3) & 1) * 16);

#pragma unroll
    for (int k0 = 0; k0 < 64; k0 += 16) {
        const uint32_t kByte = (uint32_t)(k0 * 2);
        uint32_t bh[8][2], bl[8][2];
#pragma unroll
        for (int n = 0; n < 8; ++n) {
            const uint32_t ba = sb + BH_OFF + (uint32_t)(n * 8 * ASTR * 2)
                                + bRowByte + kByte + bColByte;
            LDSM_X2(bh[n][0], bh[n][1], ba);
            LDSM_X2(bl[n][0], bl[n][1], ba + (BL_OFF - BH_OFF));
        }
#pragma unroll
        for (int s = 0; s < 2; ++s) {
            const uint32_t aa = sb + AH_OFF + aRowByte + (uint32_t)(s * 16 * ASTR * 2)
                                + kByte + aColByte;
            uint32_t ah[4], al[4];
            LDSM_X4(ah[0], ah[1], ah[2], ah[3], aa);
            LDSM_X4(al[0], al[1], al[2], al[3], aa + (AL_OFF - AH_OFF));
#pragma unroll
            for (int n = 0; n < 8; ++n) {
                MMA16816(acc[s][n], ah, bh[n]);
                MMA16816(acc[s][n], ah, bl[n]);
                MMA16816(acc[s][n], al, bh[n]);
            }
        }
    }

    uint32_t ph[2][8][2], pl[2][8][2];
#pragma unroll
    for (int s = 0; s < 2; ++s)
#pragma unroll
        for (int n = 0; n < 8; ++n) {
            pack_hl(acc[s][n][0], acc[s][n][1], ph[s][n][0], pl[s][n][0]);
            pack_hl(acc[s][n][2], acc[s][n][3], ph[s][n][1], pl[s][n][1]);
        }

    __syncthreads();
    {
        const uint4* SH4 = (const uint4*)g_sh;
        const uint4* SL4 = (const uint4*)g_sl;
#pragma unroll
        for (int i = tid; i < 512; i += 128) {
            const int off = (i >> 3) * (ASTR * 2) + ((i & 7) << 4);
            *(uint4*)(sm + BH_OFF + off) = SH4[i];
            *(uint4*)(sm + BL_OFF + off) = SL4[i];
        }
    }
    __syncthreads();

    const int g = lane >> 2, tc = lane & 3;
    float* outp = outg + t * (TRUNK * D);
#pragma unroll
    for (int s = 0; s < 2; ++s) {
        float accO[8][4];
#pragma unroll
        for (int n = 0; n < 8; ++n)
#pragma unroll
            for (int j = 0; j < 4; ++j) accO[n][j] = 0.0f;

#pragma unroll
        for (int j = 0; j < 4; ++j) {
            uint32_t ah[4] = {ph[s][2 * j][0], ph[s][2 * j][1],
                              ph[s][2 * j + 1][0], ph[s][2 * j + 1][1]};
            uint32_t al[4] = {pl[s][2 * j][0], pl[s][2 * j][1],
                              pl[s][2 * j + 1][0], pl[s][2 * j + 1][1]};
            const uint32_t kByte = (uint32_t)(j * 32);
#pragma unroll
            for (int n = 0; n < 8; ++n) {
                uint32_t bh[2], bl[2];
                const uint32_t ba = sb + BH_OFF + (uint32_t)(n * 8 * ASTR * 2)
                                    + bRowByte + kByte + bColByte;
                LDSM_X2(bh[0], bh[1], ba);
                LDSM_X2(bl[0], bl[1], ba + (BL_OFF - BH_OFF));
                MMA16816(accO[n], ah, bh);
                MMA16816(accO[n], ah, bl);
                MMA16816(accO[n], al, bh);
            }
        }

#pragma unroll
        for (int n = 0; n < 8; ++n) {
            const int col = n * 8 + tc * 2;
            const int row1 = wid * 32 + s * 16 + g;
            float2 v0; v0.x = accO[n][0]; v0.y = accO[n][1];
            float2 v1; v1.x = accO[n][2]; v1.y = accO[n][3];
            *(float2*)&outp[row1 * 64 + col]       = v0;
            *(float2*)&outp[(row1 + 8) * 64 + col] = v1;
        }
    }
}

extern "C" void kernel_launch(void* const* d_in, const int* in_sizes, int n_in,
                              void* d_out, int out_size) {
    const float* Q = (const float*)d_in[0];
    const float* K = (const float*)d_in[1];
    const float* V = (const float*)d_in[2];
    float* out = (float*)d_out;

    cudaFuncSetAttribute(kA,  cudaFuncAttributeMaxDynamicSharedMemorySize, KA_SMEM);
    cudaFuncSetAttribute(kQO, cudaFuncAttributeMaxDynamicSharedMemorySize, QO_SMEM);

    kA<<<GRID_A, 256, KA_SMEM>>>(K, V);
    kB2<<<16, 256>>>();
    kQO<<<T_TRUNKS, 128, QO_SMEM>>>(Q, out);
}

// round 17
// speedup vs baseline: 1.0444x; 1.0192x over previous
#include <cuda_runtime.h>
#include <cuda_bf16.h>
#include <cstdint>

// LinearAttentionTriton (all-HMMA):
//   M_t (bf16 hi/lo) + fp32 S-partials  -- kA (persistent, double-buffered stages)
//   S (bf16 hi/lo, transposed)          -- kB2 (deterministic reduce)
//   out_t = (Q_t @ M_t) @ S             -- kQO (mma.sync; P kept in registers)
// N = 262144, D = 64, TRUNK = 128, T = 2048.

#define D 64
#define TRUNK 128
#define T_TRUNKS 2048
#define GRID_A 444            // 148 SMs * 3 CTAs

__device__ __align__(16) uint32_t g_mh32[T_TRUNKS * 2048];   // M^T hi (bf16x2)
__device__ __align__(16) uint32_t g_ml32[T_TRUNKS * 2048];   // M^T lo
__device__ __align__(16) float g_red[512 * D * D];           // fp32 S partials
__device__ __align__(16) __nv_bfloat16 g_sh[D * D];          // S^T hi
__device__ __align__(16) __nv_bfloat16 g_sl[D * D];          // S^T lo

// ---------------- common helpers ----------------
__device__ __forceinline__ uint32_t smem_u32(const void* p) {
    uint32_t a;
    asm("{ .reg .u64 t; cvta.to.shared.u64 t, %1; cvt.u32.u64 %0, t; }"
        : "=r"(a) : "l"(p));
    return a;
}
#define LDSM_X4(r0, r1, r2, r3, a) \
    asm volatile("ldmatrix.sync.aligned.m8n8.x4.shared.b16 {%0,%1,%2,%3}, [%4];" \
                 : "=r"(r0), "=r"(r1), "=r"(r2), "=r"(r3) : "r"(a))
#define LDSM_X4_T(r0, r1, r2, r3, a) \
    asm volatile("ldmatrix.sync.aligned.m8n8.x4.trans.shared.b16 {%0,%1,%2,%3}, [%4];" \
                 : "=r"(r0), "=r"(r1), "=r"(r2), "=r"(r3) : "r"(a))
#define MMA16816(d, a, b) \
    asm volatile("mma.sync.aligned.m16n8k16.row.col.f32.bf16.bf16.f32 " \
                 "{%0,%1,%2,%3}, {%4,%5,%6,%7}, {%8,%9}, {%0,%1,%2,%3};" \
                 : "+f"((d)[0]), "+f"((d)[1]), "+f"((d)[2]), "+f"((d)[3]) \
                 : "r"((a)[0]), "r"((a)[1]), "r"((a)[2]), "r"((a)[3]), \
                   "r"((b)[0]), "r"((b)[1]))

__device__ __forceinline__ void pack_hl(float x, float y, uint32_t& h2, uint32_t& l2) {
    asm("cvt.rn.bf16x2.f32 %0, %1, %2;" : "=r"(h2) : "f"(y), "f"(x));
    const float fx = __uint_as_float(h2 << 16);
    const float fy = __uint_as_float(h2 & 0xffff0000u);
    asm("cvt.rn.bf16x2.f32 %0, %1, %2;" : "=r"(l2) : "f"(y - fy), "f"(x - fx));
}
__device__ __forceinline__ void split_quad(char* ph, char* pl, float4 v) {
    uint2 h, l;
    pack_hl(v.x, v.y, h.x, l.x);
    pack_hl(v.z, v.w, h.y, l.y);
    *(uint2*)ph = h;
    *(uint2*)pl = l;
}

// ---------------- kA: persistent, double-buffered 64-row stages ----------------
// out[m=e][n=d] = sum_r V[r][e] K[r][d]  (A = V^T, B = K^T)
#define KA_STRB 144
#define ST_KH 0
#define ST_KL 9216
#define ST_VH 18432
#define ST_VL 27648
#define KA_STAGE 36864
#define KA_SMEM 73728

__global__ void __launch_bounds__(256, 2) kA(const float* __restrict__ Kg,
                                             const float* __restrict__ Vg) {
    extern __shared__ __align__(16) char sm[];
    const uint32_t sb = smem_u32(sm);
    const int tid = threadIdx.x, lane = tid & 31, wid = tid >> 5;

    const int mt = wid & 3;            // m-tile: rows e = mt*16..+16
    const int nh = wid >> 2;           // n-half: cols d = nh*32..+32
    const int m0 = mt * 16;

    const uint32_t aOff = ST_VH
        + (uint32_t)(((lane & 7) + ((lane >> 4) << 3)) * KA_STRB)
        + (uint32_t)((m0 + ((lane >> 3) & 1) * 8) * 2);
    // X4_T B: lane groups 0/1 -> (k0,k8) at col n; groups 2/3 -> (k0,k8) at col n+8
    const uint32_t bOff4 = ST_KH
        + (uint32_t)(((lane & 7) + ((lane >> 3) & 1) * 8) * KA_STRB)
        + (uint32_t)(nh * 64) + (uint32_t)((lane >> 4) * 16);

    int so[4];
#pragma unroll
    for (int k = 0; k < 4; ++k) {
        const int i = tid + k * 256;
        so[k] = (i >> 4) * KA_STRB + ((i & 15) << 3);
    }

    float sum[4][4];
#pragma unroll
    for (int n = 0; n < 4; ++n)
#pragma unroll
        for (int j = 0; j < 4; ++j) sum[n][j] = 0.0f;

    float acc[4][4];
    const int g = lane >> 2, tc = lane & 3;

    const int nTr = (T_TRUNKS - blockIdx.x + GRID_A - 1) / GRID_A;
    const int S = nTr * 2;

    float4 kr[4], vr[4];
    {
        const float4* K4 = (const float4*)Kg + (long)blockIdx.x * 2048;
        const float4* V4 = (const float4*)Vg + (long)blockIdx.x * 2048;
#pragma unroll
        for (int k = 0; k < 4; ++k) { kr[k] = K4[tid + k * 256]; vr[k] = V4[tid + k * 256]; }
        char* base = sm;
#pragma unroll
        for (int k = 0; k < 4; ++k) {
            split_quad(base + ST_KH + so[k], base + ST_KL + so[k], kr[k]);
            split_quad(base + ST_VH + so[k], base + ST_VL + so[k], vr[k]);
        }
    }
    __syncthreads();

    for (int j = 0; j < S; ++j) {
        const int half = j & 1;
        const long t = (long)blockIdx.x + (long)(j >> 1) * GRID_A;

        const bool hasNext = (j + 1 < S);
        if (hasNext) {
            const int jn = j + 1;
            const long tn = (long)blockIdx.x + (long)(jn >> 1) * GRID_A;
            const long rbase = tn * 2048 + (long)(jn & 1) * 1024;
            const float4* K4 = (const float4*)Kg + rbase;
            const float4* V4 = (const float4*)Vg + rbase;
#pragma unroll
            for (int k = 0; k < 4; ++k) { kr[k] = K4[tid + k * 256]; vr[k] = V4[tid + k * 256]; }
        }

        if (half == 0) {
#pragma unroll
            for (int n = 0; n < 4; ++n)
#pragma unroll
                for (int jj = 0; jj < 4; ++jj) acc[n][jj] = 0.0f;
        }

        const uint32_t stBase = sb + (uint32_t)((j & 1) * KA_STAGE);
#pragma unroll
        for (int k0 = 0; k0 < 64; k0 += 16) {
            uint32_t ah[4], al[4];
            const uint32_t aa = stBase + aOff + (uint32_t)(k0 * KA_STRB);
            LDSM_X4_T(ah[0], ah[1], ah[2], ah[3], aa);
            LDSM_X4_T(al[0], al[1], al[2], al[3], aa + (ST_VL - ST_VH));
#pragma unroll
            for (int np = 0; np < 2; ++np) {
                uint32_t bh[4], bl[4];
                const uint32_t ba = stBase + bOff4 + (uint32_t)(k0 * KA_STRB)
                                    + (uint32_t)(np * 32);
                LDSM_X4_T(bh[0], bh[1], bh[2], bh[3], ba);
                LDSM_X4_T(bl[0], bl[1], bl[2], bl[3], ba + (ST_KL - ST_KH));
                MMA16816(acc[2 * np],     ah, bh);
                MMA16816(acc[2 * np],     ah, bl);
                MMA16816(acc[2 * np],     al, bh);
                MMA16816(acc[2 * np + 1], ah, bh + 2);
                MMA16816(acc[2 * np + 1], ah, bl + 2);
                MMA16816(acc[2 * np + 1], al, bh + 2);
            }
        }

        if (hasNext) {
            char* base = sm + ((j + 1) & 1) * KA_STAGE;
#pragma unroll
            for (int k = 0; k < 4; ++k) {
                split_quad(base + ST_KH + so[k], base + ST_KL + so[k], kr[k]);
                split_quad(base + ST_VH + so[k], base + ST_VL + so[k], vr[k]);
            }
        }

        if (half == 1) {
            uint32_t* mh = g_mh32 + t * 2048;
            uint32_t* ml = g_ml32 + t * 2048;
#pragma unroll
            for (int n = 0; n < 4; ++n) {
                const int col = nh * 32 + n * 8 + tc * 2;
                uint32_t h2, l2;
                pack_hl(acc[n][0], acc[n][1], h2, l2);
                mh[(m0 + g) * 32 + (col >> 1)] = h2;
                ml[(m0 + g) * 32 + (col >> 1)] = l2;
                pack_hl(acc[n][2], acc[n][3], h2, l2);
                mh[(m0 + g + 8) * 32 + (col >> 1)] = h2;
                ml[(m0 + g + 8) * 32 + (col >> 1)] = l2;
#pragma unroll
                for (int jj = 0; jj < 4; ++jj) sum[n][jj] += acc[n][jj];
            }
        }
        __syncthreads();
    }

    float* red = g_red + (long)blockIdx.x * 4096;
#pragma unroll
    for (int n = 0; n < 4; ++n) {
        const int col = nh * 32 + n * 8 + tc * 2;
        float2 v0; v0.x = sum[n][0]; v0.y = sum[n][1];
        float2 v1; v1.x = sum[n][2]; v1.y = sum[n][3];
        *(float2*)&red[(m0 + g) * 64 + col]     = v0;
        *(float2*)&red[(m0 + g + 8) * 64 + col] = v1;
    }
}

// ---------------- kB2 (unchanged) ----------------
__global__ void __launch_bounds__(256) kB2() {
    const int idx = blockIdx.x * 256 + threadIdx.x;   // idx = c*64 + e
    float s = 0.0f;
    for (int b = 0; b < GRID_A; ++b) s += g_red[(long)b * 4096 + idx];
    const int c = idx >> 6, e = idx & 63;
    const __nv_bfloat16 h = __float2bfloat16_rn(s);
    g_sh[e * 64 + c] = h;
    g_sl[e * 64 + c] = __float2bfloat16_rn(s - __bfloat162float(h));
}

// ---------------- kQO: in-register P, X4 B-loads ----------------
#define AH_OFF 0
#define AL_OFF 18432
#define BH_OFF 36864
#define BL_OFF 46080
#define QO_SMEM 55296
#define ASTR 72

__global__ void __launch_bounds__(128, 4) kQO(const float* __restrict__ Qg,
                                              float* __restrict__ outg) {
    extern __shared__ __align__(16) char sm[];
    const uint32_t sb = smem_u32(sm);
    const int tid = threadIdx.x, lane = tid & 31, wid = tid >> 5;
    const long t = blockIdx.x;

    const float4* Q4 = (const float4*)Qg + t * 2048;
#pragma unroll
    for (int i = tid; i < 2048; i += 128) {
        const int off = (i >> 4) * (ASTR * 2) + ((i & 15) << 3);
        split_quad(sm + AH_OFF + off, sm + AL_OFF + off, Q4[i]);
    }
    const uint4* MH4 = (const uint4*)g_mh32 + t * 512;
    const uint4* ML4 = (const uint4*)g_ml32 + t * 512;
#pragma unroll
    for (int i = tid; i < 512; i += 128) {
        const int off = (i >> 3) * (ASTR * 2) + ((i & 7) << 4);
        *(uint4*)(sm + BH_OFF + off) = MH4[i];
        *(uint4*)(sm + BL_OFF + off) = ML4[i];
    }
    __syncthreads();

    float acc[2][8][4];
#pragma unroll
    for (int s = 0; s < 2; ++s)
#pragma unroll
        for (int n = 0; n < 8; ++n)
#pragma unroll
            for (int j = 0; j < 4; ++j) acc[s][n][j] = 0.0f;

    const uint32_t aRowByte = (uint32_t)((wid * 32 + (lane & 15)) * (ASTR * 2));
    const uint32_t aColByte = (uint32_t)((lane >> 4) * 16);
    // X4 B: lane groups 0/1 -> rows n..n+7 at (k0, k8); groups 2/3 -> rows n+8..n+15
    const uint32_t bBase4 = (uint32_t)(((lane & 7) + (lane >> 4) * 8) * (ASTR * 2))
                            + (uint32_t)(((lane >> 3) & 1) * 16);

#pragma unroll
    for (int k0 = 0; k0 < 64; k0 += 16) {
        const uint32_t kByte = (uint32_t)(k0 * 2);
        uint32_t bh[8][2], bl[8][2];
#pragma unroll
        for (int np = 0; np < 4; ++np) {
            const uint32_t ba = sb + BH_OFF + (uint32_t)(np * 16 * ASTR * 2)
                                + bBase4 + kByte;
            LDSM_X4(bh[2 * np][0], bh[2 * np][1], bh[2 * np + 1][0], bh[2 * np + 1][1], ba);
            LDSM_X4(bl[2 * np][0], bl[2 * np][1], bl[2 * np + 1][0], bl[2 * np + 1][1],
                    ba + (BL_OFF - BH_OFF));
        }
#pragma unroll
        for (int s = 0; s < 2; ++s) {
            const uint32_t aa = sb + AH_OFF + aRowByte + (uint32_t)(s * 16 * ASTR * 2)
                                + kByte + aColByte;
            uint32_t ah[4], al[4];
            LDSM_X4(ah[0], ah[1], ah[2], ah[3], aa);
            LDSM_X4(al[0], al[1], al[2], al[3], aa + (AL_OFF - AH_OFF));
#pragma unroll
            for (int n = 0; n < 8; ++n) {
                MMA16816(acc[s][n], ah, bh[n]);
                MMA16816(acc[s][n], ah, bl[n]);
                MMA16816(acc[s][n], al, bh[n]);
            }
        }
    }

    uint32_t ph[2][8][2], pl[2][8][2];
#pragma unroll
    for (int s = 0; s < 2; ++s)
#pragma unroll
        for (int n = 0; n < 8; ++n) {
            pack_hl(acc[s][n][0], acc[s][n][1], ph[s][n][0], pl[s][n][0]);
            pack_hl(acc[s][n][2], acc[s][n][3], ph[s][n][1], pl[s][n][1]);
        }

    __syncthreads();
    {
        const uint4* SH4 = (const uint4*)g_sh;
        const uint4* SL4 = (const uint4*)g_sl;
#pragma unroll
        for (int i = tid; i < 512; i += 128) {
            const int off = (i >> 3) * (ASTR * 2) + ((i & 7) << 4);
            *(uint4*)(sm + BH_OFF + off) = SH4[i];
            *(uint4*)(sm + BL_OFF + off) = SL4[i];
        }
    }
    __syncthreads();

    const int g = lane >> 2, tc = lane & 3;
    float* outp = outg + t * (TRUNK * D);
#pragma unroll
    for (int s = 0; s < 2; ++s) {
        float accO[8][4];
#pragma unroll
        for (int n = 0; n < 8; ++n)
#pragma unroll
            for (int j = 0; j < 4; ++j) accO[n][j] = 0.0f;

#pragma unroll
        for (int j = 0; j < 4; ++j) {
            uint32_t ah[4] = {ph[s][2 * j][0], ph[s][2 * j][1],
                              ph[s][2 * j + 1][0], ph[s][2 * j + 1][1]};
            uint32_t al[4] = {pl[s][2 * j][0], pl[s][2 * j][1],
                              pl[s][2 * j + 1][0], pl[s][2 * j + 1][1]};
            const uint32_t kByte = (uint32_t)(j * 32);
#pragma unroll
            for (int np = 0; np < 4; ++np) {
                uint32_t bh[4], bl[4];
                const uint32_t ba = sb + BH_OFF + (uint32_t)(np * 16 * ASTR * 2)
                                    + bBase4 + kByte;
                LDSM_X4(bh[0], bh[1], bh[2], bh[3], ba);
                LDSM_X4(bl[0], bl[1], bl[2], bl[3], ba + (BL_OFF - BH_OFF));
                MMA16816(accO[2 * np],     ah, bh);
                MMA16816(accO[2 * np],     ah, bl);
                MMA16816(accO[2 * np],     al, bh);
                MMA16816(accO[2 * np + 1], ah, bh + 2);
                MMA16816(accO[2 * np + 1], ah, bl + 2);
                MMA16816(accO[2 * np + 1], al, bh + 2);
            }
        }

#pragma unroll
        for (int n = 0; n < 8; ++n) {
            const int col = n * 8 + tc * 2;
            const int row1 = wid * 32 + s * 16 + g;
            float2 v0; v0.x = accO[n][0]; v0.y = accO[n][1];
            float2 v1; v1.x = accO[n][2]; v1.y = accO[n][3];
            *(float2*)&outp[row1 * 64 + col]       = v0;
            *(float2*)&outp[(row1 + 8) * 64 + col] = v1;
        }
    }
}

extern "C" void kernel_launch(void* const* d_in, const int* in_sizes, int n_in,
                              void* d_out, int out_size) {
    const float* Q = (const float*)d_in[0];
    const float* K = (const float*)d_in[1];
    const float* V = (const float*)d_in[2];
    float* out = (float*)d_out;

    cudaFuncSetAttribute(kA,  cudaFuncAttributeMaxDynamicSharedMemorySize, KA_SMEM);
    cudaFuncSetAttribute(kQO, cudaFuncAttributeMaxDynamicSharedMemorySize, QO_SMEM);

    kA<<<GRID_A, 256, KA_SMEM>>>(K, V);
    kB2<<<16, 256>>>();
    kQO<<<T_TRUNKS, 128, QO_SMEM>>>(Q, out);
}